// round 2
// baseline (speedup 1.0000x reference)
#include <cuda_runtime.h>
#include <cuda_bf16.h>

#define NB 4
#define NL 2048
#define ND 1024
#define NH 16
#define DH 64

#define QT 16     // query rows per attention CTA
#define KT 256    // k/v rows per smem tile
#define SS 2052   // S row stride (floats): 2052 % 32 == 4 -> q-rows hit distinct banks
#define KS 65     // K/V tile row stride (floats): odd -> strided k-fragments conflict-free
#define SMEM_FLOATS (QT*SS + KT*KS + QT*KS + 4*QT*DH)

// Scratch (device globals — no allocation allowed in kernel_launch)
__device__ float g_k[(size_t)NB * NH * NL * DH];
__device__ float g_v[(size_t)NB * NH * NL * DH];
__device__ float g_q[(size_t)NB * NH * NL * DH];
__device__ float g_ctx[(size_t)NB * NL * ND];

// ---------------------------------------------------------------------------
// SGEMM: dst = (A[M,1024] @ W[1024,1024] + bias) * scale
// scatter=1: write to [B,H,L,dh] layout; scatter=0: plain row-major [M,1024]
// 128x128 block tile, 8x8 per-thread microtile, K-tile 8.
// ---------------------------------------------------------------------------
__global__ __launch_bounds__(256) void sgemm_bias_kernel(
    const float* __restrict__ A, const float* __restrict__ W,
    const float* __restrict__ bias, float* __restrict__ dst,
    float scale, int scatter)
{
    __shared__ float As[8][128];
    __shared__ float Bs[8][128];

    const int t  = threadIdx.x;
    const int m0 = blockIdx.y * 128;
    const int n0 = blockIdx.x * 128;
    const int ar = t >> 1, ac = (t & 1) * 4;   // A loader coords
    const int br = t >> 5, bc = (t & 31) * 4;  // B loader coords
    const int ty = t >> 4, tx = t & 15;        // compute coords

    float acc[8][8];
#pragma unroll
    for (int i = 0; i < 8; i++)
#pragma unroll
        for (int j = 0; j < 8; j++) acc[i][j] = 0.f;

    for (int k0 = 0; k0 < ND; k0 += 8) {
        float4 a4 = *(const float4*)(A + (size_t)(m0 + ar) * ND + k0 + ac);
        float4 b4 = *(const float4*)(W + (size_t)(k0 + br) * ND + n0 + bc);
        As[ac + 0][ar] = a4.x;
        As[ac + 1][ar] = a4.y;
        As[ac + 2][ar] = a4.z;
        As[ac + 3][ar] = a4.w;
        *(float4*)&Bs[br][bc] = b4;
        __syncthreads();
#pragma unroll
        for (int kk = 0; kk < 8; kk++) {
            float af[8], bf[8];
            *(float4*)&af[0] = *(const float4*)&As[kk][ty * 8];
            *(float4*)&af[4] = *(const float4*)&As[kk][ty * 8 + 4];
            *(float4*)&bf[0] = *(const float4*)&Bs[kk][tx * 8];
            *(float4*)&bf[4] = *(const float4*)&Bs[kk][tx * 8 + 4];
#pragma unroll
            for (int i = 0; i < 8; i++)
#pragma unroll
                for (int j = 0; j < 8; j++)
                    acc[i][j] = fmaf(af[i], bf[j], acc[i][j]);
        }
        __syncthreads();
    }

#pragma unroll
    for (int i = 0; i < 8; i++) {
        const int r = m0 + ty * 8 + i;
#pragma unroll
        for (int j = 0; j < 8; j++) {
            const int c = n0 + tx * 8 + j;
            const float v = (acc[i][j] + bias[c]) * scale;
            if (scatter) {
                const int b = r >> 11, l = r & (NL - 1);
                const int h = c >> 6,  d = c & 63;
                dst[((size_t)(b * NH + h) * NL + l) * DH + d] = v;
            } else {
                dst[(size_t)r * ND + c] = v;
            }
        }
    }
}

// ---------------------------------------------------------------------------
// Attention: per (b, h, 16-query tile).
// Phase 1: S[16][2048] = Qtile @ K^T      (K streamed in 256x64 smem tiles)
// Phase 2: masked softmax over smem rows  (+ write probs to gmem for h==0)
// Phase 3: ctx[16][64]  = P @ V           (V streamed, k-split x4 + reduction)
// mask is int32 (harness materializes the bool array as int32).
// ---------------------------------------------------------------------------
__global__ __launch_bounds__(256, 1) void attn_kernel(
    const int* __restrict__ mask, float* __restrict__ attn_out)
{
    extern __shared__ float sm[];
    float* S   = sm;                 // QT * SS
    float* Ks  = S  + QT * SS;       // KT * KS (reused for V tiles)
    float* Qs  = Ks + KT * KS;       // QT * KS
    float* red = Qs + QT * KS;       // 4 * QT * DH

    const int t  = threadIdx.x;
    const int q0 = blockIdx.x * QT;
    const int h  = blockIdx.y;
    const int b  = blockIdx.z;

    const float* qptr = g_q + (size_t)(b * NH + h) * NL * DH;
    const float* kptr = g_k + (size_t)(b * NH + h) * NL * DH;
    const float* vptr = g_v + (size_t)(b * NH + h) * NL * DH;

    // Load Q tile
    for (int idx = t; idx < QT * DH; idx += 256) {
        const int q = idx >> 6, d = idx & 63;
        Qs[q * KS + d] = qptr[(size_t)(q0 + q) * DH + d];
    }

    const int qg   = t >> 6;          // 0..3 : 4 q-rows each
    const int kg   = t & 63;          // 0..63: strided k columns
    const int lrow = t >> 4;          // tile loader
    const int lcol = (t & 15) * 4;

    // ---------------- Phase 1: S = Q @ K^T ----------------
    for (int kt = 0; kt < NL; kt += KT) {
        __syncthreads();
#pragma unroll
        for (int it = 0; it < KT / 16; it++) {
            const int row = it * 16 + lrow;
            const float4 v4 = *(const float4*)(kptr + (size_t)(kt + row) * DH + lcol);
            float* d2 = Ks + row * KS + lcol;
            d2[0] = v4.x; d2[1] = v4.y; d2[2] = v4.z; d2[3] = v4.w;
        }
        __syncthreads();

        const float* qp0 = Qs + (qg * 4 + 0) * KS;
        const float* qp1 = Qs + (qg * 4 + 1) * KS;
        const float* qp2 = Qs + (qg * 4 + 2) * KS;
        const float* qp3 = Qs + (qg * 4 + 3) * KS;
        const float* kp0 = Ks + (kg +   0) * KS;
        const float* kp1 = Ks + (kg +  64) * KS;
        const float* kp2 = Ks + (kg + 128) * KS;
        const float* kp3 = Ks + (kg + 192) * KS;

        float acc[4][4];
#pragma unroll
        for (int i = 0; i < 4; i++)
#pragma unroll
            for (int j = 0; j < 4; j++) acc[i][j] = 0.f;

#pragma unroll 8
        for (int dd = 0; dd < DH; dd++) {
            const float qv[4] = {qp0[dd], qp1[dd], qp2[dd], qp3[dd]};
            const float kv[4] = {kp0[dd], kp1[dd], kp2[dd], kp3[dd]};
#pragma unroll
            for (int i = 0; i < 4; i++)
#pragma unroll
                for (int j = 0; j < 4; j++)
                    acc[i][j] = fmaf(qv[i], kv[j], acc[i][j]);
        }
#pragma unroll
        for (int i = 0; i < 4; i++)
#pragma unroll
            for (int j = 0; j < 4; j++)
                S[(qg * 4 + i) * SS + kt + kg + 64 * j] = acc[i][j];
    }
    __syncthreads();

    // ---------------- Phase 2: masked softmax (2 rows per warp) ----------------
    {
        const int w = t >> 5, lane = t & 31;
#pragma unroll
        for (int rr = 0; rr < 2; rr++) {
            const int r  = w * 2 + rr;
            const int qq = q0 + r;
            const int* mrow = mask + ((size_t)b * NL + qq) * NL;
            float* srow = S + r * SS;

            float mx = -3.0e38f;
            for (int idx = lane; idx < NL; idx += 32) {
                const float s = mrow[idx] ? -1.0e18f : srow[idx];
                mx = fmaxf(mx, s);
            }
#pragma unroll
            for (int o = 16; o > 0; o >>= 1)
                mx = fmaxf(mx, __shfl_xor_sync(0xffffffffu, mx, o));

            float sum = 0.f;
            for (int idx = lane; idx < NL; idx += 32) {
                const float p = mrow[idx] ? 0.f : __expf(srow[idx] - mx);
                srow[idx] = p;
                sum += p;
            }
#pragma unroll
            for (int o = 16; o > 0; o >>= 1)
                sum += __shfl_xor_sync(0xffffffffu, sum, o);

            const float inv = 1.f / sum;
            if (h == 0) {
                float* arow = attn_out + ((size_t)b * NL + qq) * NL;
                for (int idx = lane; idx < NL; idx += 32) {
                    const float p = srow[idx] * inv;
                    srow[idx] = p;
                    arow[idx] = p;
                }
            } else {
                for (int idx = lane; idx < NL; idx += 32) srow[idx] *= inv;
            }
        }
    }

    // ---------------- Phase 3: ctx = P @ V ----------------
    const int g  = t >> 6;   // 0..3 : k-split group
    const int u  = t & 63;
    const int uq = u >> 4;   // 0..3 : 4 q-rows each
    const int ud = u & 15;   // strided d columns

    float acc3[4][4];
#pragma unroll
    for (int i = 0; i < 4; i++)
#pragma unroll
        for (int j = 0; j < 4; j++) acc3[i][j] = 0.f;

    for (int kt = 0; kt < NL; kt += KT) {
        __syncthreads();
#pragma unroll
        for (int it = 0; it < KT / 16; it++) {
            const int row = it * 16 + lrow;
            const float4 v4 = *(const float4*)(vptr + (size_t)(kt + row) * DH + lcol);
            float* d2 = Ks + row * KS + lcol;
            d2[0] = v4.x; d2[1] = v4.y; d2[2] = v4.z; d2[3] = v4.w;
        }
        __syncthreads();

        const float* p0 = S + (uq * 4 + 0) * SS + kt + g * 64;
        const float* p1 = S + (uq * 4 + 1) * SS + kt + g * 64;
        const float* p2 = S + (uq * 4 + 2) * SS + kt + g * 64;
        const float* p3 = S + (uq * 4 + 3) * SS + kt + g * 64;
        const float* vb = Ks + (g * 64) * KS + ud;

#pragma unroll 8
        for (int kk = 0; kk < 64; kk++) {
            const float pv[4] = {p0[kk], p1[kk], p2[kk], p3[kk]};
            const float* vr = vb + kk * KS;
            const float vv[4] = {vr[0], vr[16], vr[32], vr[48]};
#pragma unroll
            for (int i = 0; i < 4; i++)
#pragma unroll
                for (int j = 0; j < 4; j++)
                    acc3[i][j] = fmaf(pv[i], vv[j], acc3[i][j]);
        }
    }
    __syncthreads();
#pragma unroll
    for (int i = 0; i < 4; i++)
#pragma unroll
        for (int j = 0; j < 4; j++)
            red[(g * QT + uq * 4 + i) * DH + ud + 16 * j] = acc3[i][j];
    __syncthreads();

    float* ctx = g_ctx + (size_t)(b * NL + q0) * ND + h * DH;
    for (int idx = t; idx < QT * DH; idx += 256) {
        const int q = idx >> 6, d = idx & 63;
        const float s = red[q * DH + d] + red[(QT + q) * DH + d] +
                        red[(2 * QT + q) * DH + d] + red[(3 * QT + q) * DH + d];
        ctx[(size_t)q * ND + d] = s;
    }
}

// ---------------------------------------------------------------------------
extern "C" void kernel_launch(void* const* d_in, const int* in_sizes, int n_in,
                              void* d_out, int out_size)
{
    const float* key   = (const float*)d_in[0];
    const float* value = (const float*)d_in[1];
    const float* query = (const float*)d_in[2];
    const int*   mask  = (const int*)d_in[3];
    const float* Wk = (const float*)d_in[4];
    const float* bk = (const float*)d_in[5];
    const float* Wv = (const float*)d_in[6];
    const float* bv = (const float*)d_in[7];
    const float* Wq = (const float*)d_in[8];
    const float* bq = (const float*)d_in[9];
    const float* Wo = (const float*)d_in[10];
    const float* bo = (const float*)d_in[11];

    float* out      = (float*)d_out;
    float* attn_out = out + (size_t)NB * NL * ND;

    float *gk, *gv, *gq, *gctx;
    cudaGetSymbolAddress((void**)&gk,   g_k);
    cudaGetSymbolAddress((void**)&gv,   g_v);
    cudaGetSymbolAddress((void**)&gq,   g_q);
    cudaGetSymbolAddress((void**)&gctx, g_ctx);

    static int attr_set = 0;
    if (!attr_set) {
        cudaFuncSetAttribute(attn_kernel,
                             cudaFuncAttributeMaxDynamicSharedMemorySize,
                             SMEM_FLOATS * (int)sizeof(float));
        attr_set = 1;
    }

    const dim3 gemm_grid(ND / 128, (NB * NL) / 128);  // 8 x 64
    sgemm_bias_kernel<<<gemm_grid, 256>>>(key,   Wk, bk, gk, 1.0f,   1);
    sgemm_bias_kernel<<<gemm_grid, 256>>>(value, Wv, bv, gv, 1.0f,   1);
    sgemm_bias_kernel<<<gemm_grid, 256>>>(query, Wq, bq, gq, 0.125f, 1);

    const dim3 attn_grid(NL / QT, NH, NB);            // 128 x 16 x 4
    attn_kernel<<<attn_grid, 256, SMEM_FLOATS * (int)sizeof(float)>>>(mask, attn_out);

    sgemm_bias_kernel<<<gemm_grid, 256>>>(gctx, Wo, bo, out, 1.0f, 0);
}

// round 3
// speedup vs baseline: 1.2439x; 1.2439x over previous
#include <cuda_runtime.h>
#include <cuda_bf16.h>

#define NB 4
#define NL 2048
#define ND 1024
#define NH 16
#define DH 64

#define QT 16     // query rows per attention CTA
#define KT 256    // k/v rows per smem tile
#define SS 2052   // S row stride (floats): %32==4 -> q-rows distinct banks; %4==0 -> float4 ok
#define KS 65     // K tile row stride (scalar access, conflict-free: bank = (kg+dd)%32)
#define VS 68     // V tile row stride (float4 access: mult of 4, conflict-free per 8-lane phase)
#define SMEM_FLOATS (QT*SS + KT*VS + 64*QT + 4*QT*DH)

// ---- packed f32x2 helpers (SASS FFMA2 — only reachable via PTX) ----
__device__ __forceinline__ unsigned long long pk2(float v) {
    unsigned long long r;
    asm("mov.b64 %0, {%1, %2};" : "=l"(r) : "f"(v), "f"(v));
    return r;
}
__device__ __forceinline__ void fma2(unsigned long long& d,
                                     unsigned long long a, unsigned long long b) {
    asm("fma.rn.f32x2 %0, %1, %2, %0;" : "+l"(d) : "l"(a), "l"(b));
}
__device__ __forceinline__ void unpk(unsigned long long v, float& lo, float& hi) {
    asm("mov.b64 {%0, %1}, %2;" : "=f"(lo), "=f"(hi) : "l"(v));
}

// Scratch (device globals — no allocation allowed in kernel_launch)
__device__ float g_k[(size_t)NB * NH * NL * DH];
__device__ float g_v[(size_t)NB * NH * NL * DH];
__device__ float g_q[(size_t)NB * NH * NL * DH];
__device__ float g_ctx[(size_t)NB * NL * ND];

// ---------------------------------------------------------------------------
// SGEMM: dst = (A[M,1024] @ W[1024,1024] + bias) * scale   (packed FFMA2)
// 128x128 block tile, 8x8 per-thread microtile (as 4 i-pairs x 8 j), K-tile 8.
// ---------------------------------------------------------------------------
__global__ __launch_bounds__(256, 2) void sgemm_bias_kernel(
    const float* __restrict__ A, const float* __restrict__ W,
    const float* __restrict__ bias, float* __restrict__ dst,
    float scale, int scatter)
{
    __shared__ float As[8][128];
    __shared__ float Bs[8][128];

    const int t  = threadIdx.x;
    const int m0 = blockIdx.y * 128;
    const int n0 = blockIdx.x * 128;
    const int ar = t >> 1, ac = (t & 1) * 4;   // A loader coords
    const int br = t >> 5, bc = (t & 31) * 4;  // B loader coords
    const int ty = t >> 4, tx = t & 15;        // compute coords

    unsigned long long acc2[4][8];             // pairs over i (rows)
#pragma unroll
    for (int ip = 0; ip < 4; ip++)
#pragma unroll
        for (int j = 0; j < 8; j++) acc2[ip][j] = 0ull;

    for (int k0 = 0; k0 < ND; k0 += 8) {
        float4 a4 = *(const float4*)(A + (size_t)(m0 + ar) * ND + k0 + ac);
        float4 b4 = *(const float4*)(W + (size_t)(k0 + br) * ND + n0 + bc);
        As[ac + 0][ar] = a4.x;
        As[ac + 1][ar] = a4.y;
        As[ac + 2][ar] = a4.z;
        As[ac + 3][ar] = a4.w;
        *(float4*)&Bs[br][bc] = b4;
        __syncthreads();
#pragma unroll
        for (int kk = 0; kk < 8; kk++) {
            const ulonglong2 ap0 = *(const ulonglong2*)&As[kk][ty * 8];     // (i0,i1),(i2,i3)
            const ulonglong2 ap1 = *(const ulonglong2*)&As[kk][ty * 8 + 4]; // (i4,i5),(i6,i7)
            const float4 b0 = *(const float4*)&Bs[kk][tx * 8];
            const float4 b1 = *(const float4*)&Bs[kk][tx * 8 + 4];
            unsigned long long bd[8];
            bd[0] = pk2(b0.x); bd[1] = pk2(b0.y); bd[2] = pk2(b0.z); bd[3] = pk2(b0.w);
            bd[4] = pk2(b1.x); bd[5] = pk2(b1.y); bd[6] = pk2(b1.z); bd[7] = pk2(b1.w);
#pragma unroll
            for (int j = 0; j < 8; j++) {
                fma2(acc2[0][j], ap0.x, bd[j]);
                fma2(acc2[1][j], ap0.y, bd[j]);
                fma2(acc2[2][j], ap1.x, bd[j]);
                fma2(acc2[3][j], ap1.y, bd[j]);
            }
        }
        __syncthreads();
    }

#pragma unroll
    for (int ip = 0; ip < 4; ip++) {
#pragma unroll
        for (int j = 0; j < 8; j++) {
            float lo, hi;
            unpk(acc2[ip][j], lo, hi);
            const int c = n0 + tx * 8 + j;
            const float bias_c = bias[c];
#pragma unroll
            for (int s = 0; s < 2; s++) {
                const int r = m0 + ty * 8 + ip * 2 + s;
                const float v = ((s ? hi : lo) + bias_c) * scale;
                if (scatter) {
                    const int b = r >> 11, l = r & (NL - 1);
                    const int h = c >> 6,  d = c & 63;
                    dst[((size_t)(b * NH + h) * NL + l) * DH + d] = v;
                } else {
                    dst[(size_t)r * ND + c] = v;
                }
            }
        }
    }
}

// ---------------------------------------------------------------------------
// Attention: per (b, h, 16-query tile). Packed FFMA2 everywhere.
// Phase 1: S[16][2048] = Qtile @ K^T   (Q transposed in smem -> free q-pairs)
// Phase 2: masked softmax, float4-vectorized (+ probs to gmem for h==0)
// Phase 3: ctx = P @ V                 (consecutive d-cols -> free v-pairs)
// ---------------------------------------------------------------------------
__global__ __launch_bounds__(256, 1) void attn_kernel(
    const int* __restrict__ mask, float* __restrict__ attn_out)
{
    extern __shared__ float sm[];
    float* S   = sm;                 // QT * SS
    float* Ks  = S  + QT * SS;       // KT * VS buffer (K tiles stride KS, V tiles stride VS)
    float* Qt  = Ks + KT * VS;       // 64 * 16 (transposed Q: Qt[dd][q])
    float* red = Qt + 64 * QT;       // 4 * QT * DH

    const int t  = threadIdx.x;
    const int q0 = blockIdx.x * QT;
    const int h  = blockIdx.y;
    const int b  = blockIdx.z;

    const float* qptr = g_q + (size_t)(b * NH + h) * NL * DH;
    const float* kptr = g_k + (size_t)(b * NH + h) * NL * DH;
    const float* vptr = g_v + (size_t)(b * NH + h) * NL * DH;

    // Load Q tile transposed: Qt[dd][q]
    for (int idx = t; idx < QT * DH; idx += 256) {
        const int q = idx >> 6, d = idx & 63;
        Qt[d * QT + q] = qptr[(size_t)(q0 + q) * DH + d];
    }

    const int qg   = t >> 6;          // 0..3 : 4 q-rows each
    const int kg   = t & 63;          // 0..63: strided k columns
    const int lrow = t >> 4;          // tile loader
    const int lcol = (t & 15) * 4;

    // ---------------- Phase 1: S = Q @ K^T ----------------
    for (int kt = 0; kt < NL; kt += KT) {
        __syncthreads();
#pragma unroll
        for (int it = 0; it < KT / 16; it++) {
            const int row = it * 16 + lrow;
            const float4 v4 = *(const float4*)(kptr + (size_t)(kt + row) * DH + lcol);
            float* d2 = Ks + row * KS + lcol;
            d2[0] = v4.x; d2[1] = v4.y; d2[2] = v4.z; d2[3] = v4.w;
        }
        __syncthreads();

        unsigned long long acc2[2][4];   // 2 q-pairs x 4 k
#pragma unroll
        for (int p = 0; p < 2; p++)
#pragma unroll
            for (int j = 0; j < 4; j++) acc2[p][j] = 0ull;

#pragma unroll 4
        for (int dd = 0; dd < DH; dd++) {
            const ulonglong2 qp = *(const ulonglong2*)(Qt + dd * QT + qg * 4); // broadcast
            const float k0 = Ks[(kg      ) * KS + dd];
            const float k1 = Ks[(kg +  64) * KS + dd];
            const float k2 = Ks[(kg + 128) * KS + dd];
            const float k3 = Ks[(kg + 192) * KS + dd];
            const unsigned long long kd0 = pk2(k0), kd1 = pk2(k1);
            const unsigned long long kd2 = pk2(k2), kd3 = pk2(k3);
            fma2(acc2[0][0], qp.x, kd0); fma2(acc2[1][0], qp.y, kd0);
            fma2(acc2[0][1], qp.x, kd1); fma2(acc2[1][1], qp.y, kd1);
            fma2(acc2[0][2], qp.x, kd2); fma2(acc2[1][2], qp.y, kd2);
            fma2(acc2[0][3], qp.x, kd3); fma2(acc2[1][3], qp.y, kd3);
        }
#pragma unroll
        for (int p = 0; p < 2; p++)
#pragma unroll
            for (int j = 0; j < 4; j++) {
                float lo, hi;
                unpk(acc2[p][j], lo, hi);
                S[(qg * 4 + 2 * p    ) * SS + kt + kg + 64 * j] = lo;
                S[(qg * 4 + 2 * p + 1) * SS + kt + kg + 64 * j] = hi;
            }
    }
    __syncthreads();

    // ---------------- Phase 2: masked softmax (2 rows per warp, float4) ----------------
    {
        const int w = t >> 5, lane = t & 31;
#pragma unroll
        for (int rr = 0; rr < 2; rr++) {
            const int r  = w * 2 + rr;
            const int qq = q0 + r;
            const int4*   mrow4 = (const int4*)(mask + ((size_t)b * NL + qq) * NL);
            float4* srow4 = (float4*)(S + r * SS);

            float mx = -3.0e38f;
            for (int i = lane; i < NL / 4; i += 32) {
                const float4 s = srow4[i];
                const int4   m = mrow4[i];
                mx = fmaxf(mx, m.x ? -1.0e18f : s.x);
                mx = fmaxf(mx, m.y ? -1.0e18f : s.y);
                mx = fmaxf(mx, m.z ? -1.0e18f : s.z);
                mx = fmaxf(mx, m.w ? -1.0e18f : s.w);
            }
#pragma unroll
            for (int o = 16; o > 0; o >>= 1)
                mx = fmaxf(mx, __shfl_xor_sync(0xffffffffu, mx, o));

            float sum = 0.f;
            for (int i = lane; i < NL / 4; i += 32) {
                const float4 s = srow4[i];
                const int4   m = mrow4[i];
                float4 p;
                p.x = m.x ? 0.f : __expf(s.x - mx);
                p.y = m.y ? 0.f : __expf(s.y - mx);
                p.z = m.z ? 0.f : __expf(s.z - mx);
                p.w = m.w ? 0.f : __expf(s.w - mx);
                srow4[i] = p;
                sum += p.x + p.y + p.z + p.w;
            }
#pragma unroll
            for (int o = 16; o > 0; o >>= 1)
                sum += __shfl_xor_sync(0xffffffffu, sum, o);

            const float inv = 1.f / sum;
            if (h == 0) {
                float4* arow4 = (float4*)(attn_out + ((size_t)b * NL + qq) * NL);
                for (int i = lane; i < NL / 4; i += 32) {
                    float4 p = srow4[i];
                    p.x *= inv; p.y *= inv; p.z *= inv; p.w *= inv;
                    srow4[i] = p;
                    arow4[i] = p;
                }
            } else {
                for (int i = lane; i < NL / 4; i += 32) {
                    float4 p = srow4[i];
                    p.x *= inv; p.y *= inv; p.z *= inv; p.w *= inv;
                    srow4[i] = p;
                }
            }
        }
    }

    // ---------------- Phase 3: ctx = P @ V (k-split x4 + reduction) ----------------
    const int g  = t >> 6;   // 0..3 : k-split group
    const int u  = t & 63;
    const int uq = u >> 4;   // 0..3 : 4 q-rows each
    const int ud = u & 15;   // d block: columns 4*ud .. 4*ud+3 (consecutive)

    unsigned long long acc3[4][2];   // 4 q x 2 d-pairs
#pragma unroll
    for (int i = 0; i < 4; i++) { acc3[i][0] = 0ull; acc3[i][1] = 0ull; }

    for (int kt = 0; kt < NL; kt += KT) {
        __syncthreads();
#pragma unroll
        for (int it = 0; it < KT / 16; it++) {
            const int row = it * 16 + lrow;
            const float4 v4 = *(const float4*)(vptr + (size_t)(kt + row) * DH + lcol);
            *(float4*)(Ks + row * VS + lcol) = v4;
        }
        __syncthreads();

        const float* p0 = S + (uq * 4 + 0) * SS + kt + g * 64;
        const float* p1 = S + (uq * 4 + 1) * SS + kt + g * 64;
        const float* p2 = S + (uq * 4 + 2) * SS + kt + g * 64;
        const float* p3 = S + (uq * 4 + 3) * SS + kt + g * 64;

#pragma unroll 4
        for (int kk = 0; kk < 64; kk++) {
            const ulonglong2 vp = *(const ulonglong2*)(Ks + (g * 64 + kk) * VS + ud * 4);
            const unsigned long long pd0 = pk2(p0[kk]);
            const unsigned long long pd1 = pk2(p1[kk]);
            const unsigned long long pd2 = pk2(p2[kk]);
            const unsigned long long pd3 = pk2(p3[kk]);
            fma2(acc3[0][0], pd0, vp.x); fma2(acc3[0][1], pd0, vp.y);
            fma2(acc3[1][0], pd1, vp.x); fma2(acc3[1][1], pd1, vp.y);
            fma2(acc3[2][0], pd2, vp.x); fma2(acc3[2][1], pd2, vp.y);
            fma2(acc3[3][0], pd3, vp.x); fma2(acc3[3][1], pd3, vp.y);
        }
    }
    __syncthreads();
#pragma unroll
    for (int i = 0; i < 4; i++) {
        float* rb = red + (g * QT + uq * 4 + i) * DH + ud * 4;
        *(unsigned long long*)(rb    ) = acc3[i][0];
        *(unsigned long long*)(rb + 2) = acc3[i][1];
    }
    __syncthreads();

    float* ctx = g_ctx + (size_t)(b * NL + q0) * ND + h * DH;
    for (int idx = t; idx < QT * DH; idx += 256) {
        const int q = idx >> 6, d = idx & 63;
        const float s = red[q * DH + d] + red[(QT + q) * DH + d] +
                        red[(2 * QT + q) * DH + d] + red[(3 * QT + q) * DH + d];
        ctx[(size_t)q * ND + d] = s;
    }
}

// ---------------------------------------------------------------------------
extern "C" void kernel_launch(void* const* d_in, const int* in_sizes, int n_in,
                              void* d_out, int out_size)
{
    const float* key   = (const float*)d_in[0];
    const float* value = (const float*)d_in[1];
    const float* query = (const float*)d_in[2];
    const int*   mask  = (const int*)d_in[3];
    const float* Wk = (const float*)d_in[4];
    const float* bk = (const float*)d_in[5];
    const float* Wv = (const float*)d_in[6];
    const float* bv = (const float*)d_in[7];
    const float* Wq = (const float*)d_in[8];
    const float* bq = (const float*)d_in[9];
    const float* Wo = (const float*)d_in[10];
    const float* bo = (const float*)d_in[11];

    float* out      = (float*)d_out;
    float* attn_out = out + (size_t)NB * NL * ND;

    float *gk, *gv, *gq, *gctx;
    cudaGetSymbolAddress((void**)&gk,   g_k);
    cudaGetSymbolAddress((void**)&gv,   g_v);
    cudaGetSymbolAddress((void**)&gq,   g_q);
    cudaGetSymbolAddress((void**)&gctx, g_ctx);

    static int attr_set = 0;
    if (!attr_set) {
        cudaFuncSetAttribute(attn_kernel,
                             cudaFuncAttributeMaxDynamicSharedMemorySize,
                             SMEM_FLOATS * (int)sizeof(float));
        attr_set = 1;
    }

    const dim3 gemm_grid(ND / 128, (NB * NL) / 128);  // 8 x 64
    sgemm_bias_kernel<<<gemm_grid, 256>>>(key,   Wk, bk, gk, 1.0f,   1);
    sgemm_bias_kernel<<<gemm_grid, 256>>>(value, Wv, bv, gv, 1.0f,   1);
    sgemm_bias_kernel<<<gemm_grid, 256>>>(query, Wq, bq, gq, 0.125f, 1);

    const dim3 attn_grid(NL / QT, NH, NB);            // 128 x 16 x 4
    attn_kernel<<<attn_grid, 256, SMEM_FLOATS * (int)sizeof(float)>>>(mask, attn_out);

    sgemm_bias_kernel<<<gemm_grid, 256>>>(gctx, Wo, bo, out, 1.0f, 0);
}

// round 4
// speedup vs baseline: 1.4092x; 1.1329x over previous
#include <cuda_runtime.h>
#include <cuda_bf16.h>

#define NB 4
#define NL 2048
#define ND 1024
#define NH 16
#define DH 64

#define QT  16    // query rows per attention CTA
#define SS  2052  // S row stride: %32==4 (bank spread), %4==0 (float4 ok)
#define KT1 512   // phase-1 k-rows per tile (loaded in two 32-dd halves)
#define KSP 36    // phase-1 K tile row stride (32 dd + pad, mult of 4)
#define KT3 256   // phase-3 v-rows per tile
#define VSP 68    // phase-3 V tile row stride (mult of 4)
#define QSP 68    // Q tile row stride
#define BUFF (KT1*KSP)   // 18432 floats: holds K half-tile / V tile / reduction
#define SMEM_FLOATS (QT*SS + BUFF + QT*QSP)

// ---- packed f32x2 helpers (SASS FFMA2 — only reachable via PTX) ----
__device__ __forceinline__ unsigned long long pk2(float v) {
    unsigned long long r;
    asm("mov.b64 %0, {%1, %2};" : "=l"(r) : "f"(v), "f"(v));
    return r;
}
__device__ __forceinline__ void fma2(unsigned long long& d,
                                     unsigned long long a, unsigned long long b) {
    asm("fma.rn.f32x2 %0, %1, %2, %0;" : "+l"(d) : "l"(a), "l"(b));
}
__device__ __forceinline__ void unpk(unsigned long long v, float& lo, float& hi) {
    asm("mov.b64 {%0, %1}, %2;" : "=f"(lo), "=f"(hi) : "l"(v));
}

// Scratch (device globals — no allocation allowed in kernel_launch)
__device__ float g_k[(size_t)NB * NH * NL * DH];
__device__ float g_v[(size_t)NB * NH * NL * DH];
__device__ float g_q[(size_t)NB * NH * NL * DH];
__device__ float g_ctx[(size_t)NB * NL * ND];

// ---------------------------------------------------------------------------
// SGEMM: dst = (A[M,1024] @ W[1024,1024] + bias) * scale   (packed FFMA2)
// 128x128 block tile, 8x8 microtile, K-tile 16, double-buffered smem with
// register prefetch (hides gmem latency that bounded the previous version).
// ---------------------------------------------------------------------------
__global__ __launch_bounds__(256, 2) void sgemm_bias_kernel(
    const float* __restrict__ A, const float* __restrict__ W,
    const float* __restrict__ bias, float* __restrict__ dst,
    float scale, int scatter)
{
    __shared__ float As[2][16][128];
    __shared__ float Bs[2][16][128];

    const int t  = threadIdx.x;
    const int m0 = blockIdx.y * 128;
    const int n0 = blockIdx.x * 128;
    const int ty = t >> 4, tx = t & 15;        // compute coords

    unsigned long long acc2[4][8];             // pairs over i (rows)
#pragma unroll
    for (int ip = 0; ip < 4; ip++)
#pragma unroll
        for (int j = 0; j < 8; j++) acc2[ip][j] = 0ull;

    float4 pa[2], pb[2];
    // loader coords (idx = t + i*256)
    //   A: r = idx>>2 (0..127), c = (idx&3)*4  -> transpose-store As[c+j][r]
    //   B: br = idx>>5 (0..15), bc = (idx&31)*4 -> Bs[br][bc] float4

    // preload tile 0
#pragma unroll
    for (int i = 0; i < 2; i++) {
        const int idx = t + i * 256;
        pa[i] = *(const float4*)(A + (size_t)(m0 + (idx >> 2)) * ND + ((idx & 3) * 4));
        pb[i] = *(const float4*)(W + (size_t)(idx >> 5) * ND + n0 + (idx & 31) * 4);
    }
#pragma unroll
    for (int i = 0; i < 2; i++) {
        const int idx = t + i * 256;
        const int r = idx >> 2, c = (idx & 3) * 4;
        As[0][c + 0][r] = pa[i].x; As[0][c + 1][r] = pa[i].y;
        As[0][c + 2][r] = pa[i].z; As[0][c + 3][r] = pa[i].w;
        *(float4*)&Bs[0][idx >> 5][(idx & 31) * 4] = pb[i];
    }
    __syncthreads();

    int cur = 0;
    for (int k0 = 0; k0 < ND; k0 += 16) {
        const int has_next = (k0 + 16 < ND);
        if (has_next) {
#pragma unroll
            for (int i = 0; i < 2; i++) {
                const int idx = t + i * 256;
                pa[i] = *(const float4*)(A + (size_t)(m0 + (idx >> 2)) * ND + k0 + 16 + ((idx & 3) * 4));
                pb[i] = *(const float4*)(W + (size_t)(k0 + 16 + (idx >> 5)) * ND + n0 + (idx & 31) * 4);
            }
        }
#pragma unroll
        for (int kk = 0; kk < 16; kk++) {
            const ulonglong2 ap0 = *(const ulonglong2*)&As[cur][kk][ty * 8];
            const ulonglong2 ap1 = *(const ulonglong2*)&As[cur][kk][ty * 8 + 4];
            const float4 b0 = *(const float4*)&Bs[cur][kk][tx * 8];
            const float4 b1 = *(const float4*)&Bs[cur][kk][tx * 8 + 4];
            unsigned long long bd[8];
            bd[0] = pk2(b0.x); bd[1] = pk2(b0.y); bd[2] = pk2(b0.z); bd[3] = pk2(b0.w);
            bd[4] = pk2(b1.x); bd[5] = pk2(b1.y); bd[6] = pk2(b1.z); bd[7] = pk2(b1.w);
#pragma unroll
            for (int j = 0; j < 8; j++) {
                fma2(acc2[0][j], ap0.x, bd[j]);
                fma2(acc2[1][j], ap0.y, bd[j]);
                fma2(acc2[2][j], ap1.x, bd[j]);
                fma2(acc2[3][j], ap1.y, bd[j]);
            }
        }
        if (has_next) {
            const int nxt = cur ^ 1;
#pragma unroll
            for (int i = 0; i < 2; i++) {
                const int idx = t + i * 256;
                const int r = idx >> 2, c = (idx & 3) * 4;
                As[nxt][c + 0][r] = pa[i].x; As[nxt][c + 1][r] = pa[i].y;
                As[nxt][c + 2][r] = pa[i].z; As[nxt][c + 3][r] = pa[i].w;
                *(float4*)&Bs[nxt][idx >> 5][(idx & 31) * 4] = pb[i];
            }
        }
        __syncthreads();
        cur ^= 1;
    }

#pragma unroll
    for (int ip = 0; ip < 4; ip++) {
#pragma unroll
        for (int j = 0; j < 8; j++) {
            float lo, hi;
            unpk(acc2[ip][j], lo, hi);
            const int c = n0 + tx * 8 + j;
            const float bias_c = bias[c];
#pragma unroll
            for (int s = 0; s < 2; s++) {
                const int r = m0 + ty * 8 + ip * 2 + s;
                const float v = ((s ? hi : lo) + bias_c) * scale;
                if (scatter) {
                    const int b = r >> 11, l = r & (NL - 1);
                    const int h = c >> 6,  d = c & 63;
                    dst[((size_t)(b * NH + h) * NL + l) * DH + d] = v;
                } else {
                    dst[(size_t)r * ND + c] = v;
                }
            }
        }
    }
}

// ---------------------------------------------------------------------------
// Attention: per (b, h, 16-query tile).
// Reduction-dim FFMA2 pairing: acc lanes = (sum over even dd, sum over odd dd)
// so BOTH operands load as natural vectors — no transpose, no dup in phase 1.
// Phase 1: S = Q @ K^T   8q x 4k per thread, KT1=512 in two 32-dd halves.
// Phase 2: masked softmax (float4) + probs to gmem for h==0.
// Phase 3: ctx = P @ V   8q x 4d per thread, ksplit x8, reduction aliased.
// ---------------------------------------------------------------------------
__global__ __launch_bounds__(256, 1) void attn_kernel(
    const int* __restrict__ mask, float* __restrict__ attn_out)
{
    extern __shared__ float sm[];
    float* S   = sm;                 // QT * SS
    float* buf = S + QT * SS;        // K half-tile [512][36] / V tile [256][68] / red
    float* Qs  = buf + BUFF;         // QT * QSP

    const int t  = threadIdx.x;
    const int q0 = blockIdx.x * QT;
    const int h  = blockIdx.y;
    const int b  = blockIdx.z;

    const float* qptr = g_q + (size_t)(b * NH + h) * NL * DH;
    const float* kptr = g_k + (size_t)(b * NH + h) * NL * DH;
    const float* vptr = g_v + (size_t)(b * NH + h) * NL * DH;

    // Load Q tile [16][64] (visibility covered by first sync in phase-1 loop)
    for (int idx = t; idx < QT * DH; idx += 256) {
        const int q = idx >> 6, d = idx & 63;
        Qs[q * QSP + d] = qptr[(size_t)(q0 + q) * DH + d];
    }

    // ---------------- Phase 1: S = Q @ K^T ----------------
    {
        const int qg = t >> 7;       // 0..1 : 8 q-rows each
        const int kg = t & 127;      // 0..127: k-rows kg + 128*j

        for (int kt = 0; kt < NL; kt += KT1) {
            unsigned long long acc[8][4];
#pragma unroll
            for (int i = 0; i < 8; i++)
#pragma unroll
                for (int j = 0; j < 4; j++) acc[i][j] = 0ull;

#pragma unroll
            for (int half = 0; half < 2; half++) {
                const int dh0 = half * 32;
                __syncthreads();
                // load K half-tile [512 rows][32 dd] -> buf stride KSP
#pragma unroll
                for (int i = 0; i < 16; i++) {
                    const int idx = t + i * 256;
                    const int row = idx >> 3, c = (idx & 7) * 4;
                    const float4 v = *(const float4*)(kptr + (size_t)(kt + row) * DH + dh0 + c);
                    *(float4*)(buf + row * KSP + c) = v;
                }
                __syncthreads();

#pragma unroll
                for (int dd4 = 0; dd4 < 32; dd4 += 4) {
                    ulonglong2 kv[4];
#pragma unroll
                    for (int j = 0; j < 4; j++)
                        kv[j] = *(const ulonglong2*)(buf + (kg + 128 * j) * KSP + dd4);
#pragma unroll
                    for (int i = 0; i < 8; i++) {
                        const ulonglong2 qv =
                            *(const ulonglong2*)(Qs + (qg * 8 + i) * QSP + dh0 + dd4);
#pragma unroll
                        for (int j = 0; j < 4; j++) {
                            fma2(acc[i][j], qv.x, kv[j].x);
                            fma2(acc[i][j], qv.y, kv[j].y);
                        }
                    }
                }
            }
#pragma unroll
            for (int i = 0; i < 8; i++)
#pragma unroll
                for (int j = 0; j < 4; j++) {
                    float lo, hi;
                    unpk(acc[i][j], lo, hi);
                    S[(qg * 8 + i) * SS + kt + kg + 128 * j] = lo + hi;
                }
        }
    }
    __syncthreads();

    // ---------------- Phase 2: masked softmax (2 rows per warp, float4) ----------------
    {
        const int w = t >> 5, lane = t & 31;
#pragma unroll
        for (int rr = 0; rr < 2; rr++) {
            const int r  = w * 2 + rr;
            const int qq = q0 + r;
            const int4*   mrow4 = (const int4*)(mask + ((size_t)b * NL + qq) * NL);
            float4* srow4 = (float4*)(S + r * SS);

            float mx = -3.0e38f;
            for (int i = lane; i < NL / 4; i += 32) {
                const float4 s = srow4[i];
                const int4   m = mrow4[i];
                mx = fmaxf(mx, m.x ? -1.0e18f : s.x);
                mx = fmaxf(mx, m.y ? -1.0e18f : s.y);
                mx = fmaxf(mx, m.z ? -1.0e18f : s.z);
                mx = fmaxf(mx, m.w ? -1.0e18f : s.w);
            }
#pragma unroll
            for (int o = 16; o > 0; o >>= 1)
                mx = fmaxf(mx, __shfl_xor_sync(0xffffffffu, mx, o));

            float sum = 0.f;
            for (int i = lane; i < NL / 4; i += 32) {
                const float4 s = srow4[i];
                const int4   m = mrow4[i];
                float4 p;
                p.x = m.x ? 0.f : __expf(s.x - mx);
                p.y = m.y ? 0.f : __expf(s.y - mx);
                p.z = m.z ? 0.f : __expf(s.z - mx);
                p.w = m.w ? 0.f : __expf(s.w - mx);
                srow4[i] = p;
                sum += p.x + p.y + p.z + p.w;
            }
#pragma unroll
            for (int o = 16; o > 0; o >>= 1)
                sum += __shfl_xor_sync(0xffffffffu, sum, o);

            const float inv = 1.f / sum;
            if (h == 0) {
                float4* arow4 = (float4*)(attn_out + ((size_t)b * NL + qq) * NL);
                for (int i = lane; i < NL / 4; i += 32) {
                    float4 p = srow4[i];
                    p.x *= inv; p.y *= inv; p.z *= inv; p.w *= inv;
                    srow4[i] = p;
                    arow4[i] = p;
                }
            } else {
                for (int i = lane; i < NL / 4; i += 32) {
                    float4 p = srow4[i];
                    p.x *= inv; p.y *= inv; p.z *= inv; p.w *= inv;
                    srow4[i] = p;
                }
            }
        }
    }

    // ---------------- Phase 3: ctx = P @ V (ksplit x8 + reduction) ----------------
    {
        const int ks = t >> 5;        // 0..7 : k-chunk of 32 rows within each tile
        const int qg = (t >> 4) & 1;  // 0..1 : 8 q-rows each
        const int dg = t & 15;        // 0..15: d columns dg*4 .. dg*4+3

        unsigned long long acc[8][2];
#pragma unroll
        for (int i = 0; i < 8; i++) { acc[i][0] = 0ull; acc[i][1] = 0ull; }

        for (int kt = 0; kt < NL; kt += KT3) {
            __syncthreads();
            // load V tile [256][64] -> buf stride VSP
#pragma unroll
            for (int i = 0; i < 16; i++) {
                const int idx = t + i * 256;
                const int row = idx >> 4, c = (idx & 15) * 4;
                const float4 v = *(const float4*)(vptr + (size_t)(kt + row) * DH + c);
                *(float4*)(buf + row * VSP + c) = v;
            }
            __syncthreads();

#pragma unroll 2
            for (int kk4 = 0; kk4 < 32; kk4 += 4) {
                float4 pv[8];
#pragma unroll
                for (int i = 0; i < 8; i++)
                    pv[i] = *(const float4*)(S + (qg * 8 + i) * SS + kt + ks * 32 + kk4);
#pragma unroll
                for (int kk = 0; kk < 4; kk++) {
                    const ulonglong2 vv =
                        *(const ulonglong2*)(buf + (ks * 32 + kk4 + kk) * VSP + dg * 4);
#pragma unroll
                    for (int i = 0; i < 8; i++) {
                        const float pf = (kk == 0) ? pv[i].x : (kk == 1) ? pv[i].y
                                       : (kk == 2) ? pv[i].z : pv[i].w;
                        const unsigned long long pd = pk2(pf);
                        fma2(acc[i][0], pd, vv.x);
                        fma2(acc[i][1], pd, vv.y);
                    }
                }
            }
        }
        __syncthreads();
        // partial results: red[ks][16 q][64 d] aliased onto buf (8192 floats)
        float* red = buf;
#pragma unroll
        for (int i = 0; i < 8; i++) {
            float* rb = red + ((ks * QT) + qg * 8 + i) * DH + dg * 4;
            *(unsigned long long*)(rb)     = acc[i][0];
            *(unsigned long long*)(rb + 2) = acc[i][1];
        }
        __syncthreads();

        float* ctx = g_ctx + (size_t)(b * NL + q0) * ND + h * DH;
        for (int idx = t; idx < QT * DH; idx += 256) {
            const int q = idx >> 6, d = idx & 63;
            float s = 0.f;
#pragma unroll
            for (int g = 0; g < 8; g++) s += red[(g * QT + q) * DH + d];
            ctx[(size_t)q * ND + d] = s;
        }
    }
}

// ---------------------------------------------------------------------------
extern "C" void kernel_launch(void* const* d_in, const int* in_sizes, int n_in,
                              void* d_out, int out_size)
{
    const float* key   = (const float*)d_in[0];
    const float* value = (const float*)d_in[1];
    const float* query = (const float*)d_in[2];
    const int*   mask  = (const int*)d_in[3];
    const float* Wk = (const float*)d_in[4];
    const float* bk = (const float*)d_in[5];
    const float* Wv = (const float*)d_in[6];
    const float* bv = (const float*)d_in[7];
    const float* Wq = (const float*)d_in[8];
    const float* bq = (const float*)d_in[9];
    const float* Wo = (const float*)d_in[10];
    const float* bo = (const float*)d_in[11];

    float* out      = (float*)d_out;
    float* attn_out = out + (size_t)NB * NL * ND;

    float *gk, *gv, *gq, *gctx;
    cudaGetSymbolAddress((void**)&gk,   g_k);
    cudaGetSymbolAddress((void**)&gv,   g_v);
    cudaGetSymbolAddress((void**)&gq,   g_q);
    cudaGetSymbolAddress((void**)&gctx, g_ctx);

    static int attr_set = 0;
    if (!attr_set) {
        cudaFuncSetAttribute(attn_kernel,
                             cudaFuncAttributeMaxDynamicSharedMemorySize,
                             SMEM_FLOATS * (int)sizeof(float));
        attr_set = 1;
    }

    const dim3 gemm_grid(ND / 128, (NB * NL) / 128);  // 8 x 64
    sgemm_bias_kernel<<<gemm_grid, 256>>>(key,   Wk, bk, gk, 1.0f,   1);
    sgemm_bias_kernel<<<gemm_grid, 256>>>(value, Wv, bv, gv, 1.0f,   1);
    sgemm_bias_kernel<<<gemm_grid, 256>>>(query, Wq, bq, gq, 0.125f, 1);

    const dim3 attn_grid(NL / QT, NH, NB);            // 128 x 16 x 4
    attn_kernel<<<attn_grid, 256, SMEM_FLOATS * (int)sizeof(float)>>>(mask, attn_out);

    sgemm_bias_kernel<<<gemm_grid, 256>>>(gctx, Wo, bo, out, 1.0f, 0);
}